// round 12
// baseline (speedup 1.0000x reference)
#include <cuda_runtime.h>
#include <cuda_fp16.h>
#include <cstdint>

// ---------------- problem dims ----------------
#define MDIM 8192
#define NDIM 4096
#define KDIM 4096

// ---------------- GEMM tiling ----------------
#define BM 128
#define BN 128
#define BK 64                  // 64 fp16 = 128 B per row; tile = 16 KB
#define STAGES 3
#define KT_ITERS (KDIM / BK)   // 64
#define THREADS 128            // 4 warps: 2 (m) x 2 (n), warp tile 64x64
#define TILE_BYTES 16384

// SMEM: [0..1024) barriers, then 3 stages x (A 16KB | B 16KB)
#define SM_FULL(s)   ((s) * 8)
#define SM_EMPTY(s)  (64 + (s) * 8)
#define SM_TILE0     1024
#define OFF_A 0
#define OFF_B 16384
#define STAGE_BYTES 32768
#define SMEM_TOTAL (SM_TILE0 + STAGES * STAGE_BYTES)   // 99328 -> 2 CTAs/SM

// prep: TWO 16B units (16 fp16) per thread
#define W_PAIRS (NDIM * KDIM / 16)      // 1M
#define X_PAIRS (MDIM * KDIM / 16)      // 2M
#define W_BLOCKS (W_PAIRS / 256)        // 4096
#define X_BLOCKS (X_PAIRS / 256)        // 8192

// ---------------- scratch: pre-swizzled 16KB-tiled layouts ----------------
// g_A: [tm (64)][kt (64)] tiles; tile = 128 rows x 128B, unit u at u^(row&7)
// g_Bw: [tn (32)][kt (64)] tiles; same form
__device__ __align__(256) char g_A [(size_t)MDIM * KDIM * 2];   // 64 MB
__device__ __align__(256) char g_Bw[(size_t)NDIM * KDIM * 2];   // 32 MB

// ---------------- PTX helpers ----------------
__device__ __forceinline__ uint32_t smem_u32(const void* p) {
    return (uint32_t)__cvta_generic_to_shared(p);
}
__device__ __forceinline__ void mbar_init(uint32_t a, uint32_t cnt) {
    asm volatile("mbarrier.init.shared.b64 [%0], %1;" :: "r"(a), "r"(cnt) : "memory");
}
__device__ __forceinline__ void mbar_arrive(uint32_t a) {
    asm volatile("mbarrier.arrive.shared.b64 _, [%0];" :: "r"(a) : "memory");
}
__device__ __forceinline__ void mbar_expect_tx(uint32_t a, uint32_t bytes) {
    asm volatile("mbarrier.arrive.expect_tx.shared.b64 _, [%0], %1;"
                 :: "r"(a), "r"(bytes) : "memory");
}
__device__ __forceinline__ void bulk_g2s(uint32_t dst, const void* src,
                                         uint32_t bytes, uint32_t mbar) {
    asm volatile(
        "cp.async.bulk.shared::cluster.global.mbarrier::complete_tx::bytes "
        "[%0], [%1], %2, [%3];"
        :: "r"(dst), "l"(src), "r"(bytes), "r"(mbar) : "memory");
}
__device__ __forceinline__ void mbar_wait(uint32_t mbar, uint32_t parity) {
    asm volatile(
        "{\n\t.reg .pred P;\n\t"
        "WL%=:\n\t"
        "mbarrier.try_wait.parity.acquire.cta.shared::cta.b64 P, [%0], %1, 0x989680;\n\t"
        "@P bra.uni WD%=;\n\t"
        "bra.uni WL%=;\n\t"
        "WD%=:\n\t}"
        :: "r"(mbar), "r"(parity) : "memory");
}
__device__ __forceinline__ void mbar_wait_relaxed(uint32_t mbar, uint32_t parity) {
    asm volatile(
        "{\n\t.reg .pred P;\n\t"
        "WL%=:\n\t"
        "mbarrier.try_wait.parity.relaxed.cta.shared::cta.b64 P, [%0], %1, 0x989680;\n\t"
        "@P bra.uni WD%=;\n\t"
        "bra.uni WL%=;\n\t"
        "WD%=:\n\t}"
        :: "r"(mbar), "r"(parity) : "memory");
}
__device__ __forceinline__ void ldsm_x4(uint32_t* d, uint32_t addr) {
    asm volatile("ldmatrix.sync.aligned.m8n8.x4.shared.b16 {%0,%1,%2,%3}, [%4];"
                 : "=r"(d[0]), "=r"(d[1]), "=r"(d[2]), "=r"(d[3]) : "r"(addr));
}
__device__ __forceinline__ void mma16816(float* c, const uint32_t* a,
                                         uint32_t b0, uint32_t b1) {
    asm volatile(
        "mma.sync.aligned.m16n8k16.row.col.f32.f16.f16.f32 "
        "{%0,%1,%2,%3}, {%4,%5,%6,%7}, {%8,%9}, {%0,%1,%2,%3};"
        : "+f"(c[0]), "+f"(c[1]), "+f"(c[2]), "+f"(c[3])
        : "r"(a[0]), "r"(a[1]), "r"(a[2]), "r"(a[3]), "r"(b0), "r"(b1));
}

// ---------------- prep: emit pre-swizzled 16KB tiles, 2 units/thread --------
__global__ __launch_bounds__(256) void prep_kernel(const int* __restrict__ wp,
                                                   const float4* __restrict__ x4) {
    int bid = blockIdx.x;
    if (bid < W_BLOCKS) {
        int t = bid * 256 + threadIdx.x;       // 0 .. W_PAIRS-1
        int wu = t * 2;                        // even unit index
        int n  = wu >> 9;                      // 512 units per row (K/8)
        int ku = wu & 511;
        int4 p0 = reinterpret_cast<const int4*>(wp)[wu];
        int4 p1 = reinterpret_cast<const int4*>(wp)[wu + 1];
        __half2 h0[4], h1[4];
        h0[0] = __floats2half2_rn((float)((p0.x & 0xF) - 8), (float)(((p0.x >> 4) & 0xF) - 8));
        h0[1] = __floats2half2_rn((float)((p0.y & 0xF) - 8), (float)(((p0.y >> 4) & 0xF) - 8));
        h0[2] = __floats2half2_rn((float)((p0.z & 0xF) - 8), (float)(((p0.z >> 4) & 0xF) - 8));
        h0[3] = __floats2half2_rn((float)((p0.w & 0xF) - 8), (float)(((p0.w >> 4) & 0xF) - 8));
        h1[0] = __floats2half2_rn((float)((p1.x & 0xF) - 8), (float)(((p1.x >> 4) & 0xF) - 8));
        h1[1] = __floats2half2_rn((float)((p1.y & 0xF) - 8), (float)(((p1.y >> 4) & 0xF) - 8));
        h1[2] = __floats2half2_rn((float)((p1.z & 0xF) - 8), (float)(((p1.z >> 4) & 0xF) - 8));
        h1[3] = __floats2half2_rn((float)((p1.w & 0xF) - 8), (float)(((p1.w >> 4) & 0xF) - 8));
        int tn = n >> 7, row = n & 127, kt = ku >> 3, u = ku & 7, s = row & 7;
        size_t base = ((size_t)(tn * KT_ITERS + kt) << 14) + row * 128;
        *reinterpret_cast<uint4*>(g_Bw + base + ((u ^ s) << 4))       = *reinterpret_cast<uint4*>(h0);
        *reinterpret_cast<uint4*>(g_Bw + base + (((u + 1) ^ s) << 4)) = *reinterpret_cast<uint4*>(h1);
    } else {
        int t = (bid - W_BLOCKS) * 256 + threadIdx.x;   // 0 .. X_PAIRS-1
        int xu = t * 2;
        int m  = xu >> 9;
        int ku = xu & 511;
        float4 v0 = x4[2 * xu],     v1 = x4[2 * xu + 1];
        float4 v2 = x4[2 * xu + 2], v3 = x4[2 * xu + 3];
        __half2 h0[4], h1[4];
        h0[0] = __floats2half2_rn(v0.x, v0.y);
        h0[1] = __floats2half2_rn(v0.z, v0.w);
        h0[2] = __floats2half2_rn(v1.x, v1.y);
        h0[3] = __floats2half2_rn(v1.z, v1.w);
        h1[0] = __floats2half2_rn(v2.x, v2.y);
        h1[1] = __floats2half2_rn(v2.z, v2.w);
        h1[2] = __floats2half2_rn(v3.x, v3.y);
        h1[3] = __floats2half2_rn(v3.z, v3.w);
        int tm = m >> 7, row = m & 127, kt = ku >> 3, u = ku & 7, s = row & 7;
        size_t base = ((size_t)(tm * KT_ITERS + kt) << 14) + row * 128;
        *reinterpret_cast<uint4*>(g_A + base + ((u ^ s) << 4))       = *reinterpret_cast<uint4*>(h0);
        *reinterpret_cast<uint4*>(g_A + base + (((u + 1) ^ s) << 4)) = *reinterpret_cast<uint4*>(h1);
    }
}

// ---------------- kernel: fp16 mma.sync GEMM, TMA-bulk mbarrier ring ----------
__global__ __launch_bounds__(THREADS, 2) void gemm_kernel(
    const float* __restrict__ scales, const float* __restrict__ bias,
    float* __restrict__ out)
{
    extern __shared__ char smem[];
    const uint32_t sb = smem_u32(smem);
    const int tid = threadIdx.x;
    const int wid = tid >> 5;
    const int lane = tid & 31;

    const int tn = blockIdx.x & 31;   // 32 N-tiles (fastest -> A reuse in L2)
    const int tm = blockIdx.x >> 5;   // 64 M-tiles
    const int m0 = tm * BM;
    const int n0 = tn * BN;

    const char* gA = g_A  + ((size_t)tm * KT_ITERS << 14);
    const char* gB = g_Bw + ((size_t)tn * KT_ITERS << 14);

    const int warp_m = wid & 1;       // 2 groups of 64 rows
    const int warp_n = wid >> 1;      // 2 groups of 64 cols

    // per-lane ldmatrix addressing (swizzled: unit16 u ^ (row & 7))
    const int a_row = warp_m * 64 + (lane & 15);
    const int a_u0  = lane >> 4;                         // + 2*ks
    const int b_row = warp_n * 64 + (lane & 7) + ((lane >> 4) << 3);
    const int b_u0  = (lane >> 3) & 1;                   // + 2*ks

    if (tid == 0) {
        #pragma unroll
        for (int s = 0; s < STAGES; s++) {
            mbar_init(sb + SM_FULL(s), 1);     // one expect_tx producer
            mbar_init(sb + SM_EMPTY(s), 4);    // 4 warps release
        }
    }
    __syncthreads();   // barriers visible before any arrive / bulk

    float c[4][8][4];
    #pragma unroll
    for (int i = 0; i < 4; i++)
        #pragma unroll
        for (int j = 0; j < 8; j++)
            #pragma unroll
            for (int r = 0; r < 4; r++) c[i][j][r] = 0.0f;

    // prologue: tid0 issues bulk copies for stages 0,1
    if (tid == 0) {
        #pragma unroll
        for (int p = 0; p < STAGES - 1; p++) {
            uint32_t stg = sb + SM_TILE0 + p * STAGE_BYTES;
            mbar_expect_tx(sb + SM_FULL(p), STAGE_BYTES);
            bulk_g2s(stg + OFF_A, gA + ((size_t)p << 14), TILE_BYTES,
                     sb + SM_FULL(p));
            bulk_g2s(stg + OFF_B, gB + ((size_t)p << 14), TILE_BYTES,
                     sb + SM_FULL(p));
        }
    }

    // cursors: consumer (stage 0, phase 0); producer (stage 2, phase 1)
    int cs = 0, cph = 0;
    int ps = STAGES - 1, pph = 1;

    #pragma unroll 1
    for (int kt = 0; kt < KT_ITERS; kt++) {
        mbar_wait(sb + SM_FULL(cs), (uint32_t)cph);
        const uint32_t stg = sb + SM_TILE0 + cs * STAGE_BYTES;
        const uint32_t sA  = stg + OFF_A;
        const uint32_t sBm = stg + OFF_B;

        // ks = 0..2: load + mma
        #pragma unroll
        for (int ks = 0; ks < 3; ks++) {
            uint32_t a[4][4], b[4][4];
            #pragma unroll
            for (int i = 0; i < 4; i++) {
                int r = a_row + i * 16;
                ldsm_x4(a[i], sA + r * 128 +
                        (((uint32_t)((a_u0 + 2 * ks) ^ (r & 7))) << 4));
            }
            #pragma unroll
            for (int j = 0; j < 4; j++) {
                int r = b_row + j * 16;
                ldsm_x4(b[j], sBm + r * 128 +
                        (((uint32_t)((b_u0 + 2 * ks) ^ (r & 7))) << 4));
            }
            #pragma unroll
            for (int i = 0; i < 4; i++) {
                #pragma unroll
                for (int j = 0; j < 4; j++) {
                    mma16816(c[i][2 * j],     a[i], b[j][0], b[j][1]);
                    mma16816(c[i][2 * j + 1], a[i], b[j][2], b[j][3]);
                }
            }
        }

        // ks = 3: load fragments, release the stage EARLY, produce, then mma
        {
            uint32_t a[4][4], b[4][4];
            #pragma unroll
            for (int i = 0; i < 4; i++) {
                int r = a_row + i * 16;
                ldsm_x4(a[i], sA + r * 128 +
                        (((uint32_t)((a_u0 + 6) ^ (r & 7))) << 4));
            }
            #pragma unroll
            for (int j = 0; j < 4; j++) {
                int r = b_row + j * 16;
                ldsm_x4(b[j], sBm + r * 128 +
                        (((uint32_t)((b_u0 + 6) ^ (r & 7))) << 4));
            }
            // stage fully consumed into registers -> release now
            if (lane == 0) mbar_arrive(sb + SM_EMPTY(cs));

            // producer: refill stage for kt + STAGES - 1 while MMAs below run
            int pk = kt + STAGES - 1;
            if (pk < KT_ITERS) {
                if (tid == 0) {
                    mbar_wait_relaxed(sb + SM_EMPTY(ps), (uint32_t)pph);
                    uint32_t pstg = sb + SM_TILE0 + ps * STAGE_BYTES;
                    mbar_expect_tx(sb + SM_FULL(ps), STAGE_BYTES);
                    bulk_g2s(pstg + OFF_A, gA + ((size_t)pk << 14), TILE_BYTES,
                             sb + SM_FULL(ps));
                    bulk_g2s(pstg + OFF_B, gB + ((size_t)pk << 14), TILE_BYTES,
                             sb + SM_FULL(ps));
                }
                if (++ps == STAGES) { ps = 0; pph ^= 1; }
            }

            #pragma unroll
            for (int i = 0; i < 4; i++) {
                #pragma unroll
                for (int j = 0; j < 4; j++) {
                    mma16816(c[i][2 * j],     a[i], b[j][0], b[j][1]);
                    mma16816(c[i][2 * j + 1], a[i], b[j][2], b[j][3]);
                }
            }
        }
        if (++cs == STAGES) { cs = 0; cph ^= 1; }
    }

    // ---------------- epilogue (per-warp, no block sync): scale*acc + bias ----
    const int mrow = lane >> 2;
    const int ncol = (lane & 3) * 2;
    #pragma unroll
    for (int j = 0; j < 8; j++) {
        int n = n0 + warp_n * 64 + j * 8 + ncol;
        float2 s  = *reinterpret_cast<const float2*>(scales + n);
        float2 bb = *reinterpret_cast<const float2*>(bias + n);
        #pragma unroll
        for (int i = 0; i < 4; i++) {
            int m = m0 + warp_m * 64 + i * 16 + mrow;
            float2 v0, v1;
            v0.x = c[i][j][0] * s.x + bb.x;
            v0.y = c[i][j][1] * s.y + bb.y;
            v1.x = c[i][j][2] * s.x + bb.x;
            v1.y = c[i][j][3] * s.y + bb.y;
            *reinterpret_cast<float2*>(out + (size_t)m * NDIM + n) = v0;
            *reinterpret_cast<float2*>(out + (size_t)(m + 8) * NDIM + n) = v1;
        }
    }
}

// ---------------- launch ----------------
extern "C" void kernel_launch(void* const* d_in, const int* in_sizes, int n_in,
                              void* d_out, int out_size) {
    const float* x  = (const float*)d_in[0];
    const int*   wp = (const int*)d_in[1];
    const float* sc = (const float*)d_in[2];
    const float* bi = (const float*)d_in[3];
    float* out = (float*)d_out;

    static bool attr_set = false;
    if (!attr_set) {
        cudaFuncSetAttribute(gemm_kernel,
                             cudaFuncAttributeMaxDynamicSharedMemorySize, SMEM_TOTAL);
        attr_set = true;
    }

    prep_kernel<<<W_BLOCKS + X_BLOCKS, 256>>>(wp, (const float4*)x);
    gemm_kernel<<<(MDIM / BM) * (NDIM / BN), THREADS, SMEM_TOTAL>>>(sc, bi, out);
}

// round 13
// speedup vs baseline: 1.0425x; 1.0425x over previous
#include <cuda_runtime.h>
#include <cuda_fp16.h>
#include <cstdint>

// ---------------- problem dims ----------------
#define MDIM 8192
#define NDIM 4096
#define KDIM 4096

// ---------------- GEMM tiling ----------------
#define BM 128
#define BN 128
#define BK 64                  // 64 fp16 = 128 B per row; tile = 16 KB
#define STAGES 3
#define KT_ITERS (KDIM / BK)   // 64
#define THREADS 128            // 4 warps: 2 (m) x 2 (n), warp tile 64x64
#define TILE_BYTES 16384

// SMEM: [0..1024) barriers, then 3 stages x (A 16KB | B 16KB)
#define SM_FULL(s)   ((s) * 8)
#define SM_EMPTY(s)  (64 + (s) * 8)
#define SM_TILE0     1024
#define OFF_A 0
#define OFF_B 16384
#define STAGE_BYTES 32768
#define SMEM_TOTAL (SM_TILE0 + STAGES * STAGE_BYTES)   // 99328 -> 2 CTAs/SM

// prep: one 16B unit (8 fp16) per thread
#define W_UNITS (NDIM * KDIM / 8)       // 2M
#define X_UNITS (MDIM * KDIM / 8)       // 4M
#define W_BLOCKS (W_UNITS / 256)        // 8192
#define X_BLOCKS (X_UNITS / 256)        // 16384

// ---------------- scratch: pre-swizzled 16KB-tiled layouts ----------------
// g_A: [tm (64)][kt (64)] tiles; tile = 128 rows x 128B, unit u at u^(row&7)
// g_Bw: [tn (32)][kt (64)] tiles; same form
__device__ __align__(256) char g_A [(size_t)MDIM * KDIM * 2];   // 64 MB
__device__ __align__(256) char g_Bw[(size_t)NDIM * KDIM * 2];   // 32 MB

// ---------------- PTX helpers ----------------
__device__ __forceinline__ uint32_t smem_u32(const void* p) {
    return (uint32_t)__cvta_generic_to_shared(p);
}
__device__ __forceinline__ void mbar_init(uint32_t a, uint32_t cnt) {
    asm volatile("mbarrier.init.shared.b64 [%0], %1;" :: "r"(a), "r"(cnt) : "memory");
}
__device__ __forceinline__ void mbar_arrive(uint32_t a) {
    asm volatile("mbarrier.arrive.shared.b64 _, [%0];" :: "r"(a) : "memory");
}
__device__ __forceinline__ void mbar_expect_tx(uint32_t a, uint32_t bytes) {
    asm volatile("mbarrier.arrive.expect_tx.shared.b64 _, [%0], %1;"
                 :: "r"(a), "r"(bytes) : "memory");
}
__device__ __forceinline__ void bulk_g2s(uint32_t dst, const void* src,
                                         uint32_t bytes, uint32_t mbar) {
    asm volatile(
        "cp.async.bulk.shared::cluster.global.mbarrier::complete_tx::bytes "
        "[%0], [%1], %2, [%3];"
        :: "r"(dst), "l"(src), "r"(bytes), "r"(mbar) : "memory");
}
__device__ __forceinline__ void mbar_wait(uint32_t mbar, uint32_t parity) {
    asm volatile(
        "{\n\t.reg .pred P;\n\t"
        "WL%=:\n\t"
        "mbarrier.try_wait.parity.acquire.cta.shared::cta.b64 P, [%0], %1, 0x989680;\n\t"
        "@P bra.uni WD%=;\n\t"
        "bra.uni WL%=;\n\t"
        "WD%=:\n\t}"
        :: "r"(mbar), "r"(parity) : "memory");
}
__device__ __forceinline__ void ldsm_x4(uint32_t* d, uint32_t addr) {
    asm volatile("ldmatrix.sync.aligned.m8n8.x4.shared.b16 {%0,%1,%2,%3}, [%4];"
                 : "=r"(d[0]), "=r"(d[1]), "=r"(d[2]), "=r"(d[3]) : "r"(addr));
}
__device__ __forceinline__ void mma16816(float* c, const uint32_t* a,
                                         uint32_t b0, uint32_t b1) {
    asm volatile(
        "mma.sync.aligned.m16n8k16.row.col.f32.f16.f16.f32 "
        "{%0,%1,%2,%3}, {%4,%5,%6,%7}, {%8,%9}, {%0,%1,%2,%3};"
        : "+f"(c[0]), "+f"(c[1]), "+f"(c[2]), "+f"(c[3])
        : "r"(a[0]), "r"(a[1]), "r"(a[2]), "r"(a[3]), "r"(b0), "r"(b1));
}

// ---------------- prep: emit pre-swizzled 16KB tiles ----------------
// blocks [0, W_BLOCKS): weights. unit = 4 int32 (one byte each) -> 8 fp16 = 16B
// blocks [W_BLOCKS, +X_BLOCKS): activations. unit = 8 floats -> 8 fp16 = 16B
__global__ __launch_bounds__(256) void prep_kernel(const int* __restrict__ wp,
                                                   const float4* __restrict__ x4) {
    int bid = blockIdx.x;
    if (bid < W_BLOCKS) {
        int wu = bid * 256 + threadIdx.x;      // 0 .. W_UNITS-1
        int n  = wu >> 9;                      // 512 units per row (K/8)
        int ku = wu & 511;
        int4 p = reinterpret_cast<const int4*>(wp)[wu];   // 4 int32, contiguous
        __half2 h[4];
        h[0] = __floats2half2_rn((float)((p.x & 0xF) - 8),
                                 (float)(((p.x >> 4) & 0xF) - 8));
        h[1] = __floats2half2_rn((float)((p.y & 0xF) - 8),
                                 (float)(((p.y >> 4) & 0xF) - 8));
        h[2] = __floats2half2_rn((float)((p.z & 0xF) - 8),
                                 (float)(((p.z >> 4) & 0xF) - 8));
        h[3] = __floats2half2_rn((float)((p.w & 0xF) - 8),
                                 (float)(((p.w >> 4) & 0xF) - 8));
        int tn = n >> 7, row = n & 127, kt = ku >> 3, u = ku & 7;
        size_t dst = ((size_t)(tn * KT_ITERS + kt) << 14)
                   + row * 128 + ((u ^ (row & 7)) << 4);
        *reinterpret_cast<uint4*>(g_Bw + dst) = *reinterpret_cast<uint4*>(h);
    } else {
        int xu = (bid - W_BLOCKS) * 256 + threadIdx.x;    // 0 .. X_UNITS-1
        int m  = xu >> 9;
        int ku = xu & 511;
        float4 v0 = x4[2 * xu], v1 = x4[2 * xu + 1];
        __half2 h[4];
        h[0] = __floats2half2_rn(v0.x, v0.y);
        h[1] = __floats2half2_rn(v0.z, v0.w);
        h[2] = __floats2half2_rn(v1.x, v1.y);
        h[3] = __floats2half2_rn(v1.z, v1.w);
        int tm = m >> 7, row = m & 127, kt = ku >> 3, u = ku & 7;
        size_t dst = ((size_t)(tm * KT_ITERS + kt) << 14)
                   + row * 128 + ((u ^ (row & 7)) << 4);
        *reinterpret_cast<uint4*>(g_A + dst) = *reinterpret_cast<uint4*>(h);
    }
}

// ---------------- kernel: fp16 mma.sync GEMM, TMA-bulk ring + frag dbuf -------
__global__ __launch_bounds__(THREADS, 2) void gemm_kernel(
    const float* __restrict__ scales, const float* __restrict__ bias,
    float* __restrict__ out)
{
    extern __shared__ char smem[];
    const uint32_t sb = smem_u32(smem);
    const int tid = threadIdx.x;
    const int wid = tid >> 5;
    const int lane = tid & 31;

    const int tn = blockIdx.x & 31;   // 32 N-tiles (fastest -> A reuse in L2)
    const int tm = blockIdx.x >> 5;   // 64 M-tiles
    const int m0 = tm * BM;
    const int n0 = tn * BN;

    const char* gA = g_A  + ((size_t)tm * KT_ITERS << 14);
    const char* gB = g_Bw + ((size_t)tn * KT_ITERS << 14);

    const int warp_m = wid & 1;       // 2 groups of 64 rows
    const int warp_n = wid >> 1;      // 2 groups of 64 cols

    // per-lane ldmatrix addressing (swizzled: unit16 u ^ (row & 7))
    const int a_row = warp_m * 64 + (lane & 15);
    const int a_u0  = lane >> 4;                         // + 2*ks
    const int b_row = warp_n * 64 + (lane & 7) + ((lane >> 4) << 3);
    const int b_u0  = (lane >> 3) & 1;                   // + 2*ks

    if (tid == 0) {
        #pragma unroll
        for (int s = 0; s < STAGES; s++) {
            mbar_init(sb + SM_FULL(s), 1);     // one expect_tx producer
            mbar_init(sb + SM_EMPTY(s), 4);    // 4 warps release
        }
    }
    __syncthreads();   // barriers visible before any arrive / bulk

    float c[4][8][4];
    #pragma unroll
    for (int i = 0; i < 4; i++)
        #pragma unroll
        for (int j = 0; j < 8; j++)
            #pragma unroll
            for (int r = 0; r < 4; r++) c[i][j][r] = 0.0f;

    // prologue: tid0 issues bulk copies for stages 0,1
    if (tid == 0) {
        #pragma unroll
        for (int p = 0; p < STAGES - 1; p++) {
            uint32_t stg = sb + SM_TILE0 + p * STAGE_BYTES;
            mbar_expect_tx(sb + SM_FULL(p), STAGE_BYTES);
            bulk_g2s(stg + OFF_A, gA + ((size_t)p << 14), TILE_BYTES,
                     sb + SM_FULL(p));
            bulk_g2s(stg + OFF_B, gB + ((size_t)p << 14), TILE_BYTES,
                     sb + SM_FULL(p));
        }
    }

    // cursors: consumer (stage 0, phase 0); producer (stage 2, phase 1)
    int cs = 0, cph = 0;
    int ps = STAGES - 1, pph = 1;

    uint32_t af[2][4][4], bf[2][4][4];

    #pragma unroll 1
    for (int kt = 0; kt < KT_ITERS; kt++) {
        mbar_wait(sb + SM_FULL(cs), (uint32_t)cph);
        const uint32_t stg = sb + SM_TILE0 + cs * STAGE_BYTES;
        const uint32_t sA  = stg + OFF_A;
        const uint32_t sBm = stg + OFF_B;

        // preload ks=0 fragments
        #pragma unroll
        for (int i = 0; i < 4; i++) {
            int r = a_row + i * 16;
            ldsm_x4(af[0][i], sA + r * 128 +
                    (((uint32_t)(a_u0 ^ (r & 7))) << 4));
        }
        #pragma unroll
        for (int j = 0; j < 4; j++) {
            int r = b_row + j * 16;
            ldsm_x4(bf[0][j], sBm + r * 128 +
                    (((uint32_t)(b_u0 ^ (r & 7))) << 4));
        }

        #pragma unroll
        for (int ks = 0; ks < 4; ks++) {
            const int cur = ks & 1, nxt = cur ^ 1;
            if (ks < 3) {   // prefetch ks+1 fragments while ks MMAs issue
                #pragma unroll
                for (int i = 0; i < 4; i++) {
                    int r = a_row + i * 16;
                    ldsm_x4(af[nxt][i], sA + r * 128 +
                            (((uint32_t)((a_u0 + 2 * (ks + 1)) ^ (r & 7))) << 4));
                }
                #pragma unroll
                for (int j = 0; j < 4; j++) {
                    int r = b_row + j * 16;
                    ldsm_x4(bf[nxt][j], sBm + r * 128 +
                            (((uint32_t)((b_u0 + 2 * (ks + 1)) ^ (r & 7))) << 4));
                }
            }
            #pragma unroll
            for (int i = 0; i < 4; i++) {
                #pragma unroll
                for (int j = 0; j < 4; j++) {
                    mma16816(c[i][2 * j],     af[cur][i], bf[cur][j][0], bf[cur][j][1]);
                    mma16816(c[i][2 * j + 1], af[cur][i], bf[cur][j][2], bf[cur][j][3]);
                }
            }
        }
        // this warp is done reading stage cs
        if (lane == 0) mbar_arrive(sb + SM_EMPTY(cs));

        // produce stage for kt + STAGES - 1 (tid0 only; bulk = async proxy)
        int pk = kt + STAGES - 1;
        if (pk < KT_ITERS) {
            if (tid == 0) {
                mbar_wait(sb + SM_EMPTY(ps), (uint32_t)pph);
                uint32_t pstg = sb + SM_TILE0 + ps * STAGE_BYTES;
                mbar_expect_tx(sb + SM_FULL(ps), STAGE_BYTES);
                bulk_g2s(pstg + OFF_A, gA + ((size_t)pk << 14), TILE_BYTES,
                         sb + SM_FULL(ps));
                bulk_g2s(pstg + OFF_B, gB + ((size_t)pk << 14), TILE_BYTES,
                         sb + SM_FULL(ps));
            }
            if (++ps == STAGES) { ps = 0; pph ^= 1; }
        }
        if (++cs == STAGES) { cs = 0; cph ^= 1; }
    }

    // ---------------- epilogue (per-warp, no block sync): scale*acc + bias ----
    const int mrow = lane >> 2;
    const int ncol = (lane & 3) * 2;
    #pragma unroll
    for (int j = 0; j < 8; j++) {
        int n = n0 + warp_n * 64 + j * 8 + ncol;
        float2 s  = *reinterpret_cast<const float2*>(scales + n);
        float2 bb = *reinterpret_cast<const float2*>(bias + n);
        #pragma unroll
        for (int i = 0; i < 4; i++) {
            int m = m0 + warp_m * 64 + i * 16 + mrow;
            float2 v0, v1;
            v0.x = c[i][j][0] * s.x + bb.x;
            v0.y = c[i][j][1] * s.y + bb.y;
            v1.x = c[i][j][2] * s.x + bb.x;
            v1.y = c[i][j][3] * s.y + bb.y;
            *reinterpret_cast<float2*>(out + (size_t)m * NDIM + n) = v0;
            *reinterpret_cast<float2*>(out + (size_t)(m + 8) * NDIM + n) = v1;
        }
    }
}

// ---------------- launch ----------------
extern "C" void kernel_launch(void* const* d_in, const int* in_sizes, int n_in,
                              void* d_out, int out_size) {
    const float* x  = (const float*)d_in[0];
    const int*   wp = (const int*)d_in[1];
    const float* sc = (const float*)d_in[2];
    const float* bi = (const float*)d_in[3];
    float* out = (float*)d_out;

    static bool attr_set = false;
    if (!attr_set) {
        cudaFuncSetAttribute(gemm_kernel,
                             cudaFuncAttributeMaxDynamicSharedMemorySize, SMEM_TOTAL);
        attr_set = true;
    }

    prep_kernel<<<W_BLOCKS + X_BLOCKS, 256>>>(wp, (const float4*)x);
    gemm_kernel<<<(MDIM / BM) * (NDIM / BN), THREADS, SMEM_TOTAL>>>(sc, bi, out);
}